// round 4
// baseline (speedup 1.0000x reference)
#include <cuda_runtime.h>
#include <math.h>

#define BB   4
#define SS   1024
#define DD   512
#define HH   8
#define DKK  64
#define KTOP 204
#define PDIM 64
#define NPAT 8

typedef unsigned long long ull;

// ---- scratch ----
__device__ float g_Qf[BB*SS*DD];
__device__ float g_Kf[BB*SS*DD];
__device__ float g_Vf[BB*SS*DD];
__device__ float g_Ctx[BB*SS*DD];
__device__ float g_H1[BB*SS*PDIM];
__device__ float g_Enc[BB*SS*PDIM];
__device__ float g_S3[(size_t)BB*SS*SS];       // full-dim scores (flat 512-chain)
__device__ unsigned g_Mb[BB*SS*32];            // per-row bitmask (1024 bits)

// ---- packed f32x2 helpers ----
__device__ __forceinline__ ull ff2_pack(float lo, float hi) {
    ull r; asm("mov.b64 %0, {%1, %2};" : "=l"(r) : "f"(lo), "f"(hi)); return r;
}
__device__ __forceinline__ ull ff2_fma(ull a, ull b, ull c) {
    ull d; asm("fma.rn.f32x2 %0, %1, %2, %3;" : "=l"(d) : "l"(a), "l"(b), "l"(c)); return d;
}
__device__ __forceinline__ ull ff2_mul(ull a, ull b) {
    ull d; asm("mul.rn.f32x2 %0, %1, %2;" : "=l"(d) : "l"(a), "l"(b)); return d;
}
__device__ __forceinline__ float2 ff2_unpack(ull v) {
    float lo, hi; asm("mov.b64 {%0, %1}, %2;" : "=f"(lo), "=f"(hi) : "l"(v));
    return make_float2(lo, hi);
}

// ---------------- generic GEMM: C = act(A @ W + bias) ----------------
// Each output: ONE ascending-k fp32 FMA chain (bit-matches sgemm).
template<int ACT>
__global__ __launch_bounds__(256)
void gemm_bias_kernel(const float* __restrict__ A, const float* __restrict__ W,
                      const float* __restrict__ bias, float* __restrict__ C,
                      int M, int N, int K) {
    __shared__ __align__(16) float As[16][68];
    __shared__ __align__(16) float Bs[16][68];
    int tid = threadIdx.x;
    int tx = tid & 15, ty = tid >> 4;
    int m0 = blockIdx.y * 64, n0 = blockIdx.x * 64;
    ull acc2[4][2];
    #pragma unroll
    for (int i = 0; i < 4; i++) { acc2[i][0] = 0ull; acc2[i][1] = 0ull; }
    for (int k0 = 0; k0 < K; k0 += 16) {
        #pragma unroll
        for (int l = 0; l < 4; l++) {
            int idx = tid + l * 256;
            int r = idx >> 4, c = idx & 15;
            As[c][r] = A[(size_t)(m0 + r) * K + k0 + c];
        }
        #pragma unroll
        for (int l = 0; l < 4; l++) {
            int idx = tid + l * 256;
            int r = idx >> 6, c = idx & 63;
            Bs[r][c] = W[(size_t)(k0 + r) * N + n0 + c];
        }
        __syncthreads();
        #pragma unroll
        for (int kk = 0; kk < 16; kk++) {
            float4 a4 = *(const float4*)&As[kk][ty * 4];
            float4 b4 = *(const float4*)&Bs[kk][tx * 4];
            ull b01 = ff2_pack(b4.x, b4.y);
            ull b23 = ff2_pack(b4.z, b4.w);
            ull aa;
            aa = ff2_pack(a4.x, a4.x);
            acc2[0][0] = ff2_fma(aa, b01, acc2[0][0]);
            acc2[0][1] = ff2_fma(aa, b23, acc2[0][1]);
            aa = ff2_pack(a4.y, a4.y);
            acc2[1][0] = ff2_fma(aa, b01, acc2[1][0]);
            acc2[1][1] = ff2_fma(aa, b23, acc2[1][1]);
            aa = ff2_pack(a4.z, a4.z);
            acc2[2][0] = ff2_fma(aa, b01, acc2[2][0]);
            acc2[2][1] = ff2_fma(aa, b23, acc2[2][1]);
            aa = ff2_pack(a4.w, a4.w);
            acc2[3][0] = ff2_fma(aa, b01, acc2[3][0]);
            acc2[3][1] = ff2_fma(aa, b23, acc2[3][1]);
        }
        __syncthreads();
    }
    #pragma unroll
    for (int i = 0; i < 4; i++) {
        int m = m0 + ty * 4 + i;
        #pragma unroll
        for (int jp = 0; jp < 2; jp++) {
            float2 v2 = ff2_unpack(acc2[i][jp]);
            int n = n0 + tx * 4 + jp * 2;
            float v = v2.x + bias[n];
            if (ACT == 1) v = fmaxf(v, 0.0f);
            if (ACT == 2) v = tanhf(v);
            C[(size_t)m * N + n] = v;
            v = v2.y + bias[n + 1];
            if (ACT == 1) v = fmaxf(v, 0.0f);
            if (ACT == 2) v = tanhf(v);
            C[(size_t)m * N + n + 1] = v;
        }
    }
}

// ---------------- merged QKV projection (grid.z selects) ----------------
// FMA chain bit-identical to gemm_bias_kernel<0> (load-bearing for mask).
__global__ __launch_bounds__(256)
void qkv_kernel(const float* __restrict__ q, const float* __restrict__ k,
                const float* __restrict__ v,
                const float* __restrict__ wq, const float* __restrict__ bq,
                const float* __restrict__ wk, const float* __restrict__ bk,
                const float* __restrict__ wv, const float* __restrict__ bv,
                float* __restrict__ Qf, float* __restrict__ Kf, float* __restrict__ Vf) {
    __shared__ __align__(16) float As[16][68];
    __shared__ __align__(16) float Bs[16][68];
    const float *A, *W, *bias; float* C;
    if (blockIdx.z == 0)      { A = q; W = wq; bias = bq; C = Qf; }
    else if (blockIdx.z == 1) { A = k; W = wk; bias = bk; C = Kf; }
    else                      { A = v; W = wv; bias = bv; C = Vf; }
    const int N = DD, K = DD;
    int tid = threadIdx.x;
    int tx = tid & 15, ty = tid >> 4;
    int m0 = blockIdx.y * 64, n0 = blockIdx.x * 64;
    ull acc2[4][2];
    #pragma unroll
    for (int i = 0; i < 4; i++) { acc2[i][0] = 0ull; acc2[i][1] = 0ull; }
    for (int k0 = 0; k0 < K; k0 += 16) {
        #pragma unroll
        for (int l = 0; l < 4; l++) {
            int idx = tid + l * 256;
            int r = idx >> 4, c = idx & 15;
            As[c][r] = A[(size_t)(m0 + r) * K + k0 + c];
        }
        #pragma unroll
        for (int l = 0; l < 4; l++) {
            int idx = tid + l * 256;
            int r = idx >> 6, c = idx & 63;
            Bs[r][c] = W[(size_t)(k0 + r) * N + n0 + c];
        }
        __syncthreads();
        #pragma unroll
        for (int kk = 0; kk < 16; kk++) {
            float4 a4 = *(const float4*)&As[kk][ty * 4];
            float4 b4 = *(const float4*)&Bs[kk][tx * 4];
            ull b01 = ff2_pack(b4.x, b4.y);
            ull b23 = ff2_pack(b4.z, b4.w);
            ull aa;
            aa = ff2_pack(a4.x, a4.x);
            acc2[0][0] = ff2_fma(aa, b01, acc2[0][0]);
            acc2[0][1] = ff2_fma(aa, b23, acc2[0][1]);
            aa = ff2_pack(a4.y, a4.y);
            acc2[1][0] = ff2_fma(aa, b01, acc2[1][0]);
            acc2[1][1] = ff2_fma(aa, b23, acc2[1][1]);
            aa = ff2_pack(a4.z, a4.z);
            acc2[2][0] = ff2_fma(aa, b01, acc2[2][0]);
            acc2[2][1] = ff2_fma(aa, b23, acc2[2][1]);
            aa = ff2_pack(a4.w, a4.w);
            acc2[3][0] = ff2_fma(aa, b01, acc2[3][0]);
            acc2[3][1] = ff2_fma(aa, b23, acc2[3][1]);
        }
        __syncthreads();
    }
    #pragma unroll
    for (int i = 0; i < 4; i++) {
        int m = m0 + ty * 4 + i;
        #pragma unroll
        for (int jp = 0; jp < 2; jp++) {
            float2 v2 = ff2_unpack(acc2[i][jp]);
            int n = n0 + tx * 4 + jp * 2;
            C[(size_t)m * N + n]     = v2.x + bias[n];
            C[(size_t)m * N + n + 1] = v2.y + bias[n + 1];
        }
    }
}

// ------------- S3 only: flat ascending-k 512-chain (bit-exact, load-bearing) -------------
__global__ __launch_bounds__(256)
void s3_kernel(const float* __restrict__ Qf, const float* __restrict__ Kf,
               float* __restrict__ S3) {
    __shared__ float Qs[64][65];
    __shared__ float Ks[64][65];
    int b = blockIdx.z;
    int i0 = blockIdx.y * 64, j0 = blockIdx.x * 64;
    int tid = threadIdx.x, tx = tid & 15, ty = tid >> 4;
    ull s32[4][2];
    #pragma unroll
    for (int i = 0; i < 4; i++) { s32[i][0] = 0ull; s32[i][1] = 0ull; }
    for (int h = 0; h < HH; h++) {
        #pragma unroll
        for (int l = 0; l < 16; l++) {
            int idx = tid + l * 256;
            int r = idx >> 6, c = idx & 63;
            Qs[r][c] = Qf[(size_t)(b * SS + i0 + r) * DD + h * 64 + c];
            Ks[r][c] = Kf[(size_t)(b * SS + j0 + r) * DD + h * 64 + c];
        }
        __syncthreads();
        #pragma unroll
        for (int k = 0; k < 64; k++) {
            float a0 = Qs[ty * 4 + 0][k], a1 = Qs[ty * 4 + 1][k];
            float a2 = Qs[ty * 4 + 2][k], a3 = Qs[ty * 4 + 3][k];
            float v0 = Ks[tx * 4 + 0][k], v1 = Ks[tx * 4 + 1][k];
            float v2 = Ks[tx * 4 + 2][k], v3 = Ks[tx * 4 + 3][k];
            ull b01 = ff2_pack(v0, v1);
            ull b23 = ff2_pack(v2, v3);
            ull aa;
            aa = ff2_pack(a0, a0);
            s32[0][0] = ff2_fma(aa, b01, s32[0][0]);
            s32[0][1] = ff2_fma(aa, b23, s32[0][1]);
            aa = ff2_pack(a1, a1);
            s32[1][0] = ff2_fma(aa, b01, s32[1][0]);
            s32[1][1] = ff2_fma(aa, b23, s32[1][1]);
            aa = ff2_pack(a2, a2);
            s32[2][0] = ff2_fma(aa, b01, s32[2][0]);
            s32[2][1] = ff2_fma(aa, b23, s32[2][1]);
            aa = ff2_pack(a3, a3);
            s32[3][0] = ff2_fma(aa, b01, s32[3][0]);
            s32[3][1] = ff2_fma(aa, b23, s32[3][1]);
        }
        __syncthreads();
    }
    size_t b3 = ((size_t)b * SS + i0) * SS + j0;
    #pragma unroll
    for (int i = 0; i < 4; i++)
        #pragma unroll
        for (int jp = 0; jp < 2; jp++) {
            float2 v2 = ff2_unpack(s32[i][jp]);
            size_t o = b3 + (size_t)(ty * 4 + i) * SS + tx * 4 + jp * 2;
            S3[o]     = v2.x * 0.125f;
            S3[o + 1] = v2.y * 0.125f;
        }
}

// ------------- row-wise top-204 -> float mask (x8 heads) + bitmask -------------
__global__ __launch_bounds__(256)
void topk_mask_kernel(const float* __restrict__ S3, float* __restrict__ maskOut,
                      unsigned* __restrict__ Mb) {
    __shared__ unsigned keys[1024];
    __shared__ int hist[256];
    __shared__ unsigned s_prefix;
    __shared__ int s_rem;
    int row = blockIdx.x;          // b*SS + i
    int b = row >> 10, i = row & 1023;
    int tid = threadIdx.x;
    const float* src = S3 + (size_t)row * SS;
    #pragma unroll
    for (int l = 0; l < 4; l++) {
        int j = tid + l * 256;
        unsigned bits = __float_as_uint(src[j]);
        keys[j] = (bits & 0x80000000u) ? ~bits : (bits | 0x80000000u);
    }
    if (tid == 0) { s_prefix = 0u; s_rem = KTOP; }
    __syncthreads();
    for (int pass = 0; pass < 4; pass++) {
        int shift = 24 - pass * 8;
        hist[tid] = 0;
        __syncthreads();
        unsigned pref = s_prefix;
        #pragma unroll
        for (int l = 0; l < 4; l++) {
            unsigned key = keys[tid + l * 256];
            bool match = (pass == 0) || ((key >> (shift + 8)) == (pref >> (shift + 8)));
            if (match) atomicAdd(&hist[(key >> shift) & 255], 1);
        }
        __syncthreads();
        if (tid == 0) {
            int c = 0, rem = s_rem; unsigned chosen = 0;
            for (int bin = 255; bin >= 0; bin--) {
                c += hist[bin];
                if (c >= rem) { chosen = (unsigned)bin; s_rem = rem - (c - hist[bin]); break; }
            }
            s_prefix = pref | (chosen << shift);
        }
        __syncthreads();
    }
    unsigned T = s_prefix;
    int need = s_rem;
    size_t maskBase = (size_t)b * HH * SS * SS + (size_t)i * SS;
    #pragma unroll
    for (int l = 0; l < 4; l++) {
        int j = tid + l * 256;
        unsigned key = keys[j];
        float m = 0.0f;
        if (key > T) m = 1.0f;
        else if (key == T) {
            int cnt = 0;
            for (int jj = 0; jj < j; jj++) cnt += (keys[jj] == T) ? 1 : 0;
            if (cnt < need) m = 1.0f;
        }
        unsigned bal = __ballot_sync(0xffffffffu, m > 0.0f);
        if ((tid & 31) == 0)
            Mb[(size_t)row * 32 + l * 8 + (tid >> 5)] = bal;
        #pragma unroll
        for (int h = 0; h < HH; h++)
            maskOut[maskBase + (size_t)h * SS * SS + j] = m;
    }
}

// ------------- fused attention: recompute scores, masked online softmax, P@V -------------
// Ctx[b,i,h*64+d] = softmax_j(mask(QK/8))[i,j] @ Vh[j,d]
__global__ __launch_bounds__(256)
void fused_attn_kernel(const float* __restrict__ Qf, const float* __restrict__ Kf,
                       const float* __restrict__ Vf, const unsigned* __restrict__ Mb,
                       float* __restrict__ Ctx) {
    extern __shared__ float sm[];
    float* Qs = sm;                       // [64][64]
    float* Ks = sm + 64 * 64;             // [64][65], reused as P tile
    float* Vs = sm + 64 * 64 + 64 * 65;   // [64][64], float4-aligned
    const int QSS = 64, KSS = 65, VSS = 64;
    int bh = blockIdx.y;
    int b = bh >> 3, h = bh & 7;
    int i0 = blockIdx.x * 64;
    int tid = threadIdx.x, tx = tid & 15, ty = tid >> 4;
    #pragma unroll
    for (int l = 0; l < 16; l++) {
        int idx = tid + l * 256;
        int r = idx >> 6, c = idx & 63;
        Qs[r * QSS + c] = Qf[(size_t)(b * SS + i0 + r) * DD + h * 64 + c];
    }
    float m_old[4] = {-INFINITY, -INFINITY, -INFINITY, -INFINITY};
    float l_run[4] = {0.f, 0.f, 0.f, 0.f};
    ull accO[4][2];
    #pragma unroll
    for (int i = 0; i < 4; i++) { accO[i][0] = 0ull; accO[i][1] = 0ull; }

    for (int j0 = 0; j0 < SS; j0 += 64) {
        __syncthreads();   // protect Ks(P)/Vs from previous iteration's PV reads
        #pragma unroll
        for (int l = 0; l < 16; l++) {
            int idx = tid + l * 256;
            int r = idx >> 6, c = idx & 63;
            Ks[r * KSS + c] = Kf[(size_t)(b * SS + j0 + r) * DD + h * 64 + c];
            Vs[r * VSS + c] = Vf[(size_t)(b * SS + j0 + r) * DD + h * 64 + c];
        }
        __syncthreads();
        // ---- QK tile ----
        ull acc2[4][2];
        #pragma unroll
        for (int i = 0; i < 4; i++) { acc2[i][0] = 0ull; acc2[i][1] = 0ull; }
        #pragma unroll
        for (int k = 0; k < 64; k++) {
            float a0 = Qs[(ty * 4 + 0) * QSS + k], a1 = Qs[(ty * 4 + 1) * QSS + k];
            float a2 = Qs[(ty * 4 + 2) * QSS + k], a3 = Qs[(ty * 4 + 3) * QSS + k];
            float v0 = Ks[(tx * 4 + 0) * KSS + k], v1 = Ks[(tx * 4 + 1) * KSS + k];
            float v2 = Ks[(tx * 4 + 2) * KSS + k], v3 = Ks[(tx * 4 + 3) * KSS + k];
            ull b01 = ff2_pack(v0, v1);
            ull b23 = ff2_pack(v2, v3);
            ull aa;
            aa = ff2_pack(a0, a0);
            acc2[0][0] = ff2_fma(aa, b01, acc2[0][0]);
            acc2[0][1] = ff2_fma(aa, b23, acc2[0][1]);
            aa = ff2_pack(a1, a1);
            acc2[1][0] = ff2_fma(aa, b01, acc2[1][0]);
            acc2[1][1] = ff2_fma(aa, b23, acc2[1][1]);
            aa = ff2_pack(a2, a2);
            acc2[2][0] = ff2_fma(aa, b01, acc2[2][0]);
            acc2[2][1] = ff2_fma(aa, b23, acc2[2][1]);
            aa = ff2_pack(a3, a3);
            acc2[3][0] = ff2_fma(aa, b01, acc2[3][0]);
            acc2[3][1] = ff2_fma(aa, b23, acc2[3][1]);
        }
        // ---- unpack, scale, mask ----
        float s[4][4];
        #pragma unroll
        for (int i = 0; i < 4; i++) {
            float2 v0 = ff2_unpack(acc2[i][0]);
            float2 v1 = ff2_unpack(acc2[i][1]);
            s[i][0] = v0.x * 0.125f; s[i][1] = v0.y * 0.125f;
            s[i][2] = v1.x * 0.125f; s[i][3] = v1.y * 0.125f;
        }
        #pragma unroll
        for (int i = 0; i < 4; i++) {
            int r = i0 + ty * 4 + i;
            unsigned w = Mb[((size_t)(b * SS + r)) * 32 + (j0 >> 5) + (tx >> 3)];
            #pragma unroll
            for (int j = 0; j < 4; j++)
                if (!((w >> ((tx * 4 + j) & 31)) & 1u)) s[i][j] = -INFINITY;
        }
        // ---- online softmax update (row stats across the 16 tx lanes) ----
        #pragma unroll
        for (int i = 0; i < 4; i++) {
            float r = fmaxf(fmaxf(s[i][0], s[i][1]), fmaxf(s[i][2], s[i][3]));
            #pragma unroll
            for (int d = 1; d < 16; d <<= 1)
                r = fmaxf(r, __shfl_xor_sync(0xffffffffu, r, d));
            float mn = fmaxf(m_old[i], r);
            float sc = (m_old[i] == -INFINITY) ? 0.0f : expf(m_old[i] - mn);
            float rs = 0.0f;
            #pragma unroll
            for (int j = 0; j < 4; j++) {
                float p = (s[i][j] == -INFINITY) ? 0.0f : expf(s[i][j] - mn);
                s[i][j] = p;
                rs += p;
            }
            #pragma unroll
            for (int d = 1; d < 16; d <<= 1)
                rs += __shfl_xor_sync(0xffffffffu, rs, d);
            l_run[i] = l_run[i] * sc + rs;
            m_old[i] = mn;
            ull sc2 = ff2_pack(sc, sc);
            accO[i][0] = ff2_mul(sc2, accO[i][0]);
            accO[i][1] = ff2_mul(sc2, accO[i][1]);
        }
        __syncthreads();   // everyone done reading Ks before overwriting with P
        #pragma unroll
        for (int i = 0; i < 4; i++)
            #pragma unroll
            for (int j = 0; j < 4; j++)
                Ks[(ty * 4 + i) * KSS + tx * 4 + j] = s[i][j];
        __syncthreads();
        // ---- P @ V accumulate ----
        #pragma unroll 16
        for (int kk = 0; kk < 64; kk++) {
            float a0 = Ks[(ty * 4 + 0) * KSS + kk], a1 = Ks[(ty * 4 + 1) * KSS + kk];
            float a2 = Ks[(ty * 4 + 2) * KSS + kk], a3 = Ks[(ty * 4 + 3) * KSS + kk];
            float4 v4 = *(const float4*)&Vs[kk * VSS + tx * 4];
            ull b01 = ff2_pack(v4.x, v4.y);
            ull b23 = ff2_pack(v4.z, v4.w);
            ull aa;
            aa = ff2_pack(a0, a0);
            accO[0][0] = ff2_fma(aa, b01, accO[0][0]);
            accO[0][1] = ff2_fma(aa, b23, accO[0][1]);
            aa = ff2_pack(a1, a1);
            accO[1][0] = ff2_fma(aa, b01, accO[1][0]);
            accO[1][1] = ff2_fma(aa, b23, accO[1][1]);
            aa = ff2_pack(a2, a2);
            accO[2][0] = ff2_fma(aa, b01, accO[2][0]);
            accO[2][1] = ff2_fma(aa, b23, accO[2][1]);
            aa = ff2_pack(a3, a3);
            accO[3][0] = ff2_fma(aa, b01, accO[3][0]);
            accO[3][1] = ff2_fma(aa, b23, accO[3][1]);
        }
    }
    #pragma unroll
    for (int i = 0; i < 4; i++) {
        float inv = 1.0f / l_run[i];
        #pragma unroll
        for (int jp = 0; jp < 2; jp++) {
            float2 v2 = ff2_unpack(accO[i][jp]);
            size_t o = (size_t)(b * SS + i0 + ty * 4 + i) * DD + h * 64 + tx * 4 + jp * 2;
            Ctx[o]     = v2.x * inv;
            Ctx[o + 1] = v2.y * inv;
        }
    }
}

// ------------- pattern head: softmax(enc@bank^T/8) * gate -------------
__global__ __launch_bounds__(256)
void pattern_kernel(const float* __restrict__ Enc, const float* __restrict__ bank,
                    const float* __restrict__ gate, float* __restrict__ outP) {
    int r = blockIdx.x * blockDim.x + threadIdx.x;
    if (r >= BB * SS) return;
    const float* e = Enc + (size_t)r * PDIM;
    float s[NPAT];
    float mx = -1e30f;
    #pragma unroll
    for (int p = 0; p < NPAT; p++) {
        float d = 0.0f;
        for (int k = 0; k < PDIM; k++) d = fmaf(e[k], bank[p * PDIM + k], d);
        s[p] = d * 0.125f;
        mx = fmaxf(mx, s[p]);
    }
    float sum = 0.0f;
    #pragma unroll
    for (int p = 0; p < NPAT; p++) { s[p] = expf(s[p] - mx); sum += s[p]; }
    #pragma unroll
    for (int p = 0; p < NPAT; p++)
        outP[(size_t)r * NPAT + p] = s[p] / sum * gate[p];
}

extern "C" void kernel_launch(void* const* d_in, const int* in_sizes, int n_in,
                              void* d_out, int out_size) {
    const float* query = (const float*)d_in[0];
    const float* key   = (const float*)d_in[1];
    const float* value = (const float*)d_in[2];
    const float* wq = (const float*)d_in[3];  const float* bq = (const float*)d_in[4];
    const float* wk = (const float*)d_in[5];  const float* bk = (const float*)d_in[6];
    const float* wv = (const float*)d_in[7];  const float* bv = (const float*)d_in[8];
    const float* wo = (const float*)d_in[9];  const float* bo = (const float*)d_in[10];
    const float* pw1 = (const float*)d_in[11]; const float* pb1 = (const float*)d_in[12];
    const float* pw2 = (const float*)d_in[13]; const float* pb2 = (const float*)d_in[14];
    const float* bank = (const float*)d_in[15];
    const float* gate = (const float*)d_in[16];
    float* out = (float*)d_out;

    void *pQf, *pKf, *pVf, *pCtx, *pH1, *pEnc, *pS3, *pMb;
    cudaGetSymbolAddress(&pQf, g_Qf);
    cudaGetSymbolAddress(&pKf, g_Kf);
    cudaGetSymbolAddress(&pVf, g_Vf);
    cudaGetSymbolAddress(&pCtx, g_Ctx);
    cudaGetSymbolAddress(&pH1, g_H1);
    cudaGetSymbolAddress(&pEnc, g_Enc);
    cudaGetSymbolAddress(&pS3, g_S3);
    cudaGetSymbolAddress(&pMb, g_Mb);
    float* Qf = (float*)pQf;   float* Kf = (float*)pKf;
    float* Vf = (float*)pVf;   float* Ctx = (float*)pCtx;
    float* H1 = (float*)pH1;   float* Enc = (float*)pEnc;
    float* S3 = (float*)pS3;   unsigned* Mb = (unsigned*)pMb;

    const size_t maskOff  = (size_t)BB * SS * DD;
    const size_t patOff   = maskOff + (size_t)BB * HH * SS * SS;
    float* outAttn = out;
    float* outMask = out + maskOff;
    float* outPat  = out + patOff;

    const int M = BB * SS;   // 4096
    dim3 blk(256);

    // fused kernel needs 49408 B dynamic smem (> 48K default)
    const int FUSED_SMEM = (64 * 64 + 64 * 65 + 64 * 64) * 4;
    cudaFuncSetAttribute(fused_attn_kernel,
                         cudaFuncAttributeMaxDynamicSharedMemorySize, FUSED_SMEM);

    // QKV projections (one launch, bit-exact chains)
    qkv_kernel<<<dim3(DD / 64, M / 64, 3), blk>>>(query, key, value,
                                                  wq, bq, wk, bk, wv, bv,
                                                  Qf, Kf, Vf);

    // pattern MLP
    gemm_bias_kernel<1><<<dim3(PDIM / 64, M / 64), blk>>>(query, pw1, pb1, H1, M, PDIM, DD);
    gemm_bias_kernel<2><<<dim3(PDIM / 64, M / 64), blk>>>(H1, pw2, pb2, Enc, M, PDIM, PDIM);
    pattern_kernel<<<dim3(M / 256), blk>>>(Enc, bank, gate, outPat);

    // flat-chain full-dim scores (S3 only)
    s3_kernel<<<dim3(SS / 64, SS / 64, BB), blk>>>(Qf, Kf, S3);

    // top-204: float mask output (x8 heads) + bitmask scratch
    topk_mask_kernel<<<dim3(BB * SS), blk>>>(S3, outMask, Mb);

    // fused scores-recompute + masked online softmax + P@V
    fused_attn_kernel<<<dim3(SS / 64, BB * HH), blk, FUSED_SMEM>>>(Qf, Kf, Vf, Mb, Ctx);

    // output projection
    gemm_bias_kernel<0><<<dim3(DD / 64, M / 64), blk>>>(Ctx, wo, bo, outAttn, M, DD, DD);
}

// round 5
// speedup vs baseline: 1.0273x; 1.0273x over previous
#include <cuda_runtime.h>
#include <math.h>

#define BB   4
#define SS   1024
#define DD   512
#define HH   8
#define DKK  64
#define KTOP 204
#define PDIM 64
#define NPAT 8

typedef unsigned long long ull;

// ---- scratch ----
__device__ float g_Qf[BB*SS*DD];
__device__ float g_Kf[BB*SS*DD];
__device__ float g_Vf[BB*SS*DD];
__device__ float g_Ctx[BB*SS*DD];
__device__ float g_Sc[(size_t)BB*HH*SS*SS];    // per-head scores
__device__ float g_S3[(size_t)BB*SS*SS];       // full-dim scores (flat 512-chain)
__device__ unsigned g_Mb[BB*SS*32];            // per-row bitmask (1024 bits)

// ---- packed f32x2 helpers ----
__device__ __forceinline__ ull ff2_pack(float lo, float hi) {
    ull r; asm("mov.b64 %0, {%1, %2};" : "=l"(r) : "f"(lo), "f"(hi)); return r;
}
__device__ __forceinline__ ull ff2_fma(ull a, ull b, ull c) {
    ull d; asm("fma.rn.f32x2 %0, %1, %2, %3;" : "=l"(d) : "l"(a), "l"(b), "l"(c)); return d;
}
__device__ __forceinline__ float2 ff2_unpack(ull v) {
    float lo, hi; asm("mov.b64 {%0, %1}, %2;" : "=f"(lo), "=f"(hi) : "l"(v));
    return make_float2(lo, hi);
}

// ---------------- generic GEMM: C = act(A @ W + bias) ----------------
template<int ACT>
__global__ __launch_bounds__(256)
void gemm_bias_kernel(const float* __restrict__ A, const float* __restrict__ W,
                      const float* __restrict__ bias, float* __restrict__ C,
                      int M, int N, int K) {
    __shared__ __align__(16) float As[16][68];
    __shared__ __align__(16) float Bs[16][68];
    int tid = threadIdx.x;
    int tx = tid & 15, ty = tid >> 4;
    int m0 = blockIdx.y * 64, n0 = blockIdx.x * 64;
    ull acc2[4][2];
    #pragma unroll
    for (int i = 0; i < 4; i++) { acc2[i][0] = 0ull; acc2[i][1] = 0ull; }
    for (int k0 = 0; k0 < K; k0 += 16) {
        #pragma unroll
        for (int l = 0; l < 4; l++) {
            int idx = tid + l * 256;
            int r = idx >> 4, c = idx & 15;
            As[c][r] = A[(size_t)(m0 + r) * K + k0 + c];
        }
        #pragma unroll
        for (int l = 0; l < 4; l++) {
            int idx = tid + l * 256;
            int r = idx >> 6, c = idx & 63;
            Bs[r][c] = W[(size_t)(k0 + r) * N + n0 + c];
        }
        __syncthreads();
        #pragma unroll
        for (int kk = 0; kk < 16; kk++) {
            float4 a4 = *(const float4*)&As[kk][ty * 4];
            float4 b4 = *(const float4*)&Bs[kk][tx * 4];
            ull b01 = ff2_pack(b4.x, b4.y);
            ull b23 = ff2_pack(b4.z, b4.w);
            ull aa;
            aa = ff2_pack(a4.x, a4.x);
            acc2[0][0] = ff2_fma(aa, b01, acc2[0][0]);
            acc2[0][1] = ff2_fma(aa, b23, acc2[0][1]);
            aa = ff2_pack(a4.y, a4.y);
            acc2[1][0] = ff2_fma(aa, b01, acc2[1][0]);
            acc2[1][1] = ff2_fma(aa, b23, acc2[1][1]);
            aa = ff2_pack(a4.z, a4.z);
            acc2[2][0] = ff2_fma(aa, b01, acc2[2][0]);
            acc2[2][1] = ff2_fma(aa, b23, acc2[2][1]);
            aa = ff2_pack(a4.w, a4.w);
            acc2[3][0] = ff2_fma(aa, b01, acc2[3][0]);
            acc2[3][1] = ff2_fma(aa, b23, acc2[3][1]);
        }
        __syncthreads();
    }
    #pragma unroll
    for (int i = 0; i < 4; i++) {
        int m = m0 + ty * 4 + i;
        #pragma unroll
        for (int jp = 0; jp < 2; jp++) {
            float2 v2 = ff2_unpack(acc2[i][jp]);
            int n = n0 + tx * 4 + jp * 2;
            float v = v2.x + bias[n];
            if (ACT == 1) v = fmaxf(v, 0.0f);
            if (ACT == 2) v = tanhf(v);
            C[(size_t)m * N + n] = v;
            v = v2.y + bias[n + 1];
            if (ACT == 1) v = fmaxf(v, 0.0f);
            if (ACT == 2) v = tanhf(v);
            C[(size_t)m * N + n + 1] = v;
        }
    }
}

// ---------------- merged QKV projection (grid.z selects) ----------------
// FMA chain bit-identical across rounds (load-bearing for the mask).
__global__ __launch_bounds__(256)
void qkv_kernel(const float* __restrict__ q, const float* __restrict__ k,
                const float* __restrict__ v,
                const float* __restrict__ wq, const float* __restrict__ bq,
                const float* __restrict__ wk, const float* __restrict__ bk,
                const float* __restrict__ wv, const float* __restrict__ bv,
                float* __restrict__ Qf, float* __restrict__ Kf, float* __restrict__ Vf) {
    __shared__ __align__(16) float As[16][68];
    __shared__ __align__(16) float Bs[16][68];
    const float *A, *W, *bias; float* C;
    if (blockIdx.z == 0)      { A = q; W = wq; bias = bq; C = Qf; }
    else if (blockIdx.z == 1) { A = k; W = wk; bias = bk; C = Kf; }
    else                      { A = v; W = wv; bias = bv; C = Vf; }
    const int N = DD, K = DD;
    int tid = threadIdx.x;
    int tx = tid & 15, ty = tid >> 4;
    int m0 = blockIdx.y * 64, n0 = blockIdx.x * 64;
    ull acc2[4][2];
    #pragma unroll
    for (int i = 0; i < 4; i++) { acc2[i][0] = 0ull; acc2[i][1] = 0ull; }
    for (int k0 = 0; k0 < K; k0 += 16) {
        #pragma unroll
        for (int l = 0; l < 4; l++) {
            int idx = tid + l * 256;
            int r = idx >> 4, c = idx & 15;
            As[c][r] = A[(size_t)(m0 + r) * K + k0 + c];
        }
        #pragma unroll
        for (int l = 0; l < 4; l++) {
            int idx = tid + l * 256;
            int r = idx >> 6, c = idx & 63;
            Bs[r][c] = W[(size_t)(k0 + r) * N + n0 + c];
        }
        __syncthreads();
        #pragma unroll
        for (int kk = 0; kk < 16; kk++) {
            float4 a4 = *(const float4*)&As[kk][ty * 4];
            float4 b4 = *(const float4*)&Bs[kk][tx * 4];
            ull b01 = ff2_pack(b4.x, b4.y);
            ull b23 = ff2_pack(b4.z, b4.w);
            ull aa;
            aa = ff2_pack(a4.x, a4.x);
            acc2[0][0] = ff2_fma(aa, b01, acc2[0][0]);
            acc2[0][1] = ff2_fma(aa, b23, acc2[0][1]);
            aa = ff2_pack(a4.y, a4.y);
            acc2[1][0] = ff2_fma(aa, b01, acc2[1][0]);
            acc2[1][1] = ff2_fma(aa, b23, acc2[1][1]);
            aa = ff2_pack(a4.z, a4.z);
            acc2[2][0] = ff2_fma(aa, b01, acc2[2][0]);
            acc2[2][1] = ff2_fma(aa, b23, acc2[2][1]);
            aa = ff2_pack(a4.w, a4.w);
            acc2[3][0] = ff2_fma(aa, b01, acc2[3][0]);
            acc2[3][1] = ff2_fma(aa, b23, acc2[3][1]);
        }
        __syncthreads();
    }
    #pragma unroll
    for (int i = 0; i < 4; i++) {
        int m = m0 + ty * 4 + i;
        #pragma unroll
        for (int jp = 0; jp < 2; jp++) {
            float2 v2 = ff2_unpack(acc2[i][jp]);
            int n = n0 + tx * 4 + jp * 2;
            C[(size_t)m * N + n]     = v2.x + bias[n];
            C[(size_t)m * N + n + 1] = v2.y + bias[n + 1];
        }
    }
}

// ------------- per-head scores + full-dim flat-chain sum: Sc, S3 -------------
// S3: ONE fp32 FMA chain in strictly ascending k (bit-exact, load-bearing).
__global__ __launch_bounds__(256)
void scores_kernel(const float* __restrict__ Qf, const float* __restrict__ Kf,
                   float* __restrict__ Sc, float* __restrict__ S3) {
    __shared__ float Qs[64][65];
    __shared__ float Ks[64][65];
    int b = blockIdx.z;
    int i0 = blockIdx.y * 64, j0 = blockIdx.x * 64;
    int tid = threadIdx.x, tx = tid & 15, ty = tid >> 4;
    ull s32[4][2];
    #pragma unroll
    for (int i = 0; i < 4; i++) { s32[i][0] = 0ull; s32[i][1] = 0ull; }
    for (int h = 0; h < HH; h++) {
        #pragma unroll
        for (int l = 0; l < 16; l++) {
            int idx = tid + l * 256;
            int r = idx >> 6, c = idx & 63;
            Qs[r][c] = Qf[(size_t)(b * SS + i0 + r) * DD + h * 64 + c];
            Ks[r][c] = Kf[(size_t)(b * SS + j0 + r) * DD + h * 64 + c];
        }
        __syncthreads();
        ull acc2[4][2];
        #pragma unroll
        for (int i = 0; i < 4; i++) { acc2[i][0] = 0ull; acc2[i][1] = 0ull; }
        #pragma unroll
        for (int k = 0; k < 64; k++) {
            float a0 = Qs[ty * 4 + 0][k], a1 = Qs[ty * 4 + 1][k];
            float a2 = Qs[ty * 4 + 2][k], a3 = Qs[ty * 4 + 3][k];
            float v0 = Ks[tx * 4 + 0][k], v1 = Ks[tx * 4 + 1][k];
            float v2 = Ks[tx * 4 + 2][k], v3 = Ks[tx * 4 + 3][k];
            ull b01 = ff2_pack(v0, v1);
            ull b23 = ff2_pack(v2, v3);
            ull aa;
            aa = ff2_pack(a0, a0);
            acc2[0][0] = ff2_fma(aa, b01, acc2[0][0]);
            acc2[0][1] = ff2_fma(aa, b23, acc2[0][1]);
            s32[0][0]  = ff2_fma(aa, b01, s32[0][0]);
            s32[0][1]  = ff2_fma(aa, b23, s32[0][1]);
            aa = ff2_pack(a1, a1);
            acc2[1][0] = ff2_fma(aa, b01, acc2[1][0]);
            acc2[1][1] = ff2_fma(aa, b23, acc2[1][1]);
            s32[1][0]  = ff2_fma(aa, b01, s32[1][0]);
            s32[1][1]  = ff2_fma(aa, b23, s32[1][1]);
            aa = ff2_pack(a2, a2);
            acc2[2][0] = ff2_fma(aa, b01, acc2[2][0]);
            acc2[2][1] = ff2_fma(aa, b23, acc2[2][1]);
            s32[2][0]  = ff2_fma(aa, b01, s32[2][0]);
            s32[2][1]  = ff2_fma(aa, b23, s32[2][1]);
            aa = ff2_pack(a3, a3);
            acc2[3][0] = ff2_fma(aa, b01, acc2[3][0]);
            acc2[3][1] = ff2_fma(aa, b23, acc2[3][1]);
            s32[3][0]  = ff2_fma(aa, b01, s32[3][0]);
            s32[3][1]  = ff2_fma(aa, b23, s32[3][1]);
        }
        size_t base = (((size_t)(b * HH + h) * SS + i0) * SS) + j0;
        #pragma unroll
        for (int i = 0; i < 4; i++)
            #pragma unroll
            for (int jp = 0; jp < 2; jp++) {
                float2 v2 = ff2_unpack(acc2[i][jp]);
                size_t o = base + (size_t)(ty * 4 + i) * SS + tx * 4 + jp * 2;
                Sc[o]     = v2.x * 0.125f;
                Sc[o + 1] = v2.y * 0.125f;
            }
        __syncthreads();
    }
    size_t b3 = ((size_t)b * SS + i0) * SS + j0;
    #pragma unroll
    for (int i = 0; i < 4; i++)
        #pragma unroll
        for (int jp = 0; jp < 2; jp++) {
            float2 v2 = ff2_unpack(s32[i][jp]);
            size_t o = b3 + (size_t)(ty * 4 + i) * SS + tx * 4 + jp * 2;
            S3[o]     = v2.x * 0.125f;
            S3[o + 1] = v2.y * 0.125f;
        }
}

// ------------- row-wise top-204 -> float mask (x8 heads) + bitmask -------------
__global__ __launch_bounds__(256)
void topk_mask_kernel(const float* __restrict__ S3, float* __restrict__ maskOut,
                      unsigned* __restrict__ Mb) {
    __shared__ unsigned keys[1024];
    __shared__ int hist[256];
    __shared__ unsigned s_prefix;
    __shared__ int s_rem;
    int row = blockIdx.x;
    int b = row >> 10, i = row & 1023;
    int tid = threadIdx.x;
    const float* src = S3 + (size_t)row * SS;
    #pragma unroll
    for (int l = 0; l < 4; l++) {
        int j = tid + l * 256;
        unsigned bits = __float_as_uint(src[j]);
        keys[j] = (bits & 0x80000000u) ? ~bits : (bits | 0x80000000u);
    }
    if (tid == 0) { s_prefix = 0u; s_rem = KTOP; }
    __syncthreads();
    for (int pass = 0; pass < 4; pass++) {
        int shift = 24 - pass * 8;
        hist[tid] = 0;
        __syncthreads();
        unsigned pref = s_prefix;
        #pragma unroll
        for (int l = 0; l < 4; l++) {
            unsigned key = keys[tid + l * 256];
            bool match = (pass == 0) || ((key >> (shift + 8)) == (pref >> (shift + 8)));
            if (match) atomicAdd(&hist[(key >> shift) & 255], 1);
        }
        __syncthreads();
        if (tid == 0) {
            int c = 0, rem = s_rem; unsigned chosen = 0;
            for (int bin = 255; bin >= 0; bin--) {
                c += hist[bin];
                if (c >= rem) { chosen = (unsigned)bin; s_rem = rem - (c - hist[bin]); break; }
            }
            s_prefix = pref | (chosen << shift);
        }
        __syncthreads();
    }
    unsigned T = s_prefix;
    int need = s_rem;
    size_t maskBase = (size_t)b * HH * SS * SS + (size_t)i * SS;
    #pragma unroll
    for (int l = 0; l < 4; l++) {
        int j = tid + l * 256;
        unsigned key = keys[j];
        float m = 0.0f;
        if (key > T) m = 1.0f;
        else if (key == T) {
            int cnt = 0;
            for (int jj = 0; jj < j; jj++) cnt += (keys[jj] == T) ? 1 : 0;
            if (cnt < need) m = 1.0f;
        }
        unsigned bal = __ballot_sync(0xffffffffu, m > 0.0f);
        if ((tid & 31) == 0)
            Mb[(size_t)row * 32 + l * 8 + (tid >> 5)] = bal;
        #pragma unroll
        for (int h = 0; h < HH; h++)
            maskOut[maskBase + (size_t)h * SS * SS + j] = m;
    }
}

// ------------- av_exp: p = mask ? exp(Sc) : 0; Ctx = (p @ V) / rowsum(p) -------------
// No max-subtraction needed: scores are O(1), exp cannot overflow; identical to
// softmax-with-max up to ~1e-7 rounding. Row sum accumulated in the PV loop
// (each thread reads its full P-row slice -> broadcast, no reduction needed).
__global__ __launch_bounds__(256)
void av_exp_kernel(const float* __restrict__ Sc, const float* __restrict__ Vf,
                   const unsigned* __restrict__ Mb, float* __restrict__ Ctx) {
    __shared__ float Ps[64][65];
    __shared__ __align__(16) float Vs[64][68];
    int bh = blockIdx.y;
    int b = bh >> 3, h = bh & 7;
    int i0 = blockIdx.x * 64;
    int tid = threadIdx.x, tx = tid & 15, ty = tid >> 4;
    ull accO[4][2];
    #pragma unroll
    for (int i = 0; i < 4; i++) { accO[i][0] = 0ull; accO[i][1] = 0ull; }
    float rs[4] = {0.f, 0.f, 0.f, 0.f};
    const float* Prow = Sc + ((size_t)bh * SS + i0) * SS;
    for (int k0 = 0; k0 < SS; k0 += 64) {
        __syncthreads();
        #pragma unroll
        for (int l = 0; l < 16; l++) {
            int idx = tid + l * 256;
            int r = idx >> 6, c = idx & 63;
            float s = Prow[(size_t)r * SS + k0 + c];
            unsigned w = Mb[(size_t)(b * SS + i0 + r) * 32 + ((k0 + c) >> 5)];
            Ps[r][c] = ((w >> ((k0 + c) & 31)) & 1u) ? __expf(s) : 0.0f;
            Vs[r][c] = Vf[(size_t)(b * SS + k0 + r) * DD + h * 64 + c];
        }
        __syncthreads();
        #pragma unroll 16
        for (int kk = 0; kk < 64; kk++) {
            float a0 = Ps[ty * 4 + 0][kk], a1 = Ps[ty * 4 + 1][kk];
            float a2 = Ps[ty * 4 + 2][kk], a3 = Ps[ty * 4 + 3][kk];
            rs[0] += a0; rs[1] += a1; rs[2] += a2; rs[3] += a3;
            float4 v4 = *(const float4*)&Vs[kk][tx * 4];
            ull b01 = ff2_pack(v4.x, v4.y);
            ull b23 = ff2_pack(v4.z, v4.w);
            ull aa;
            aa = ff2_pack(a0, a0);
            accO[0][0] = ff2_fma(aa, b01, accO[0][0]);
            accO[0][1] = ff2_fma(aa, b23, accO[0][1]);
            aa = ff2_pack(a1, a1);
            accO[1][0] = ff2_fma(aa, b01, accO[1][0]);
            accO[1][1] = ff2_fma(aa, b23, accO[1][1]);
            aa = ff2_pack(a2, a2);
            accO[2][0] = ff2_fma(aa, b01, accO[2][0]);
            accO[2][1] = ff2_fma(aa, b23, accO[2][1]);
            aa = ff2_pack(a3, a3);
            accO[3][0] = ff2_fma(aa, b01, accO[3][0]);
            accO[3][1] = ff2_fma(aa, b23, accO[3][1]);
        }
    }
    #pragma unroll
    for (int i = 0; i < 4; i++) {
        float inv = 1.0f / rs[i];
        #pragma unroll
        for (int jp = 0; jp < 2; jp++) {
            float2 v2 = ff2_unpack(accO[i][jp]);
            size_t o = (size_t)(b * SS + i0 + ty * 4 + i) * DD + h * 64 + tx * 4 + jp * 2;
            Ctx[o]     = v2.x * inv;
            Ctx[o + 1] = v2.y * inv;
        }
    }
}

// ------------- fused pattern branch: relu(q@pw1+pb1)@pw2+pb2 -> tanh -> softmax*gate -------------
__global__ __launch_bounds__(256)
void pattern_fused_kernel(const float* __restrict__ q,
                          const float* __restrict__ pw1, const float* __restrict__ pb1,
                          const float* __restrict__ pw2, const float* __restrict__ pb2,
                          const float* __restrict__ bank, const float* __restrict__ gate,
                          float* __restrict__ outP) {
    __shared__ float As[16][33];   // q panel: [k][row] 32 rows
    __shared__ float Bs[16][65];   // weight panel 16x64
    __shared__ float H1[32][65];
    __shared__ float Enc[32][65];
    int tid = threadIdx.x, tx = tid & 15, ty = tid >> 4;
    int m0 = blockIdx.x * 32;
    // stage 1: H1 = relu(q @ pw1 + pb1)   (32 x 64, K=512)
    float acc[2][4] = {};
    for (int k0 = 0; k0 < DD; k0 += 16) {
        #pragma unroll
        for (int l = 0; l < 2; l++) {
            int idx = tid + l * 256;
            int r = idx >> 4, c = idx & 15;
            As[c][r] = q[(size_t)(m0 + r) * DD + k0 + c];
        }
        #pragma unroll
        for (int l = 0; l < 4; l++) {
            int idx = tid + l * 256;
            int r = idx >> 6, c = idx & 63;
            Bs[r][c] = pw1[(size_t)(k0 + r) * PDIM + c];
        }
        __syncthreads();
        #pragma unroll
        for (int kk = 0; kk < 16; kk++) {
            float a0 = As[kk][ty * 2], a1 = As[kk][ty * 2 + 1];
            #pragma unroll
            for (int j = 0; j < 4; j++) {
                float bb = Bs[kk][tx * 4 + j];
                acc[0][j] = fmaf(a0, bb, acc[0][j]);
                acc[1][j] = fmaf(a1, bb, acc[1][j]);
            }
        }
        __syncthreads();
    }
    #pragma unroll
    for (int i = 0; i < 2; i++)
        #pragma unroll
        for (int j = 0; j < 4; j++)
            H1[ty * 2 + i][tx * 4 + j] = fmaxf(acc[i][j] + pb1[tx * 4 + j], 0.0f);
    __syncthreads();
    // stage 2: Enc = tanh(H1 @ pw2 + pb2)   (32 x 64, K=64)
    float acc2[2][4] = {};
    for (int k0 = 0; k0 < PDIM; k0 += 16) {
        #pragma unroll
        for (int l = 0; l < 4; l++) {
            int idx = tid + l * 256;
            int r = idx >> 6, c = idx & 63;
            Bs[idx >> 6][c] = pw2[(size_t)(k0 + r) * PDIM + c];
        }
        __syncthreads();
        #pragma unroll
        for (int kk = 0; kk < 16; kk++) {
            float a0 = H1[ty * 2][k0 + kk], a1 = H1[ty * 2 + 1][k0 + kk];
            #pragma unroll
            for (int j = 0; j < 4; j++) {
                float bb = Bs[kk][tx * 4 + j];
                acc2[0][j] = fmaf(a0, bb, acc2[0][j]);
                acc2[1][j] = fmaf(a1, bb, acc2[1][j]);
            }
        }
        __syncthreads();
    }
    #pragma unroll
    for (int i = 0; i < 2; i++)
        #pragma unroll
        for (int j = 0; j < 4; j++)
            Enc[ty * 2 + i][tx * 4 + j] = tanhf(acc2[i][j] + pb2[tx * 4 + j]);
    __syncthreads();
    // stage 3: per (row, pattern) score -> softmax over 8 -> * gate
    int row = tid >> 3, p = tid & 7;
    float d = 0.0f;
    #pragma unroll
    for (int k = 0; k < PDIM; k++)
        d = fmaf(Enc[row][k], bank[p * PDIM + k], d);
    float s = d * 0.125f;
    float mx = s;
    #pragma unroll
    for (int o = 1; o < 8; o <<= 1) mx = fmaxf(mx, __shfl_xor_sync(0xffffffffu, mx, o));
    float e = expf(s - mx);
    float sum = e;
    #pragma unroll
    for (int o = 1; o < 8; o <<= 1) sum += __shfl_xor_sync(0xffffffffu, sum, o);
    outP[(size_t)(m0 + row) * NPAT + p] = e / sum * gate[p];
}

extern "C" void kernel_launch(void* const* d_in, const int* in_sizes, int n_in,
                              void* d_out, int out_size) {
    const float* query = (const float*)d_in[0];
    const float* key   = (const float*)d_in[1];
    const float* value = (const float*)d_in[2];
    const float* wq = (const float*)d_in[3];  const float* bq = (const float*)d_in[4];
    const float* wk = (const float*)d_in[5];  const float* bk = (const float*)d_in[6];
    const float* wv = (const float*)d_in[7];  const float* bv = (const float*)d_in[8];
    const float* wo = (const float*)d_in[9];  const float* bo = (const float*)d_in[10];
    const float* pw1 = (const float*)d_in[11]; const float* pb1 = (const float*)d_in[12];
    const float* pw2 = (const float*)d_in[13]; const float* pb2 = (const float*)d_in[14];
    const float* bank = (const float*)d_in[15];
    const float* gate = (const float*)d_in[16];
    float* out = (float*)d_out;

    void *pQf, *pKf, *pVf, *pCtx, *pSc, *pS3, *pMb;
    cudaGetSymbolAddress(&pQf, g_Qf);
    cudaGetSymbolAddress(&pKf, g_Kf);
    cudaGetSymbolAddress(&pVf, g_Vf);
    cudaGetSymbolAddress(&pCtx, g_Ctx);
    cudaGetSymbolAddress(&pSc, g_Sc);
    cudaGetSymbolAddress(&pS3, g_S3);
    cudaGetSymbolAddress(&pMb, g_Mb);
    float* Qf = (float*)pQf;   float* Kf = (float*)pKf;
    float* Vf = (float*)pVf;   float* Ctx = (float*)pCtx;
    float* Sc = (float*)pSc;   float* S3 = (float*)pS3;
    unsigned* Mb = (unsigned*)pMb;

    const size_t maskOff  = (size_t)BB * SS * DD;
    const size_t patOff   = maskOff + (size_t)BB * HH * SS * SS;
    float* outAttn = out;
    float* outMask = out + maskOff;
    float* outPat  = out + patOff;

    const int M = BB * SS;   // 4096
    dim3 blk(256);

    // QKV projections (one launch, bit-exact chains)
    qkv_kernel<<<dim3(DD / 64, M / 64, 3), blk>>>(query, key, value,
                                                  wq, bq, wk, bk, wv, bv,
                                                  Qf, Kf, Vf);

    // fused pattern branch (independent of QKV)
    pattern_fused_kernel<<<dim3(M / 32), blk>>>(query, pw1, pb1, pw2, pb2,
                                                bank, gate, outPat);

    // per-head scores + flat-chain full-dim scores (dual, bit-exact S3)
    scores_kernel<<<dim3(SS / 64, SS / 64, BB), blk>>>(Qf, Kf, Sc, S3);

    // top-204: float mask output (x8 heads) + bitmask scratch
    topk_mask_kernel<<<dim3(BB * SS), blk>>>(S3, outMask, Mb);

    // masked exp + P@V + rowsum-normalize (softmax without max-pass)
    av_exp_kernel<<<dim3(SS / 64, BB * HH), blk>>>(Sc, Vf, Mb, Ctx);

    // output projection
    gemm_bias_kernel<0><<<dim3(DD / 64, M / 64), blk>>>(Ctx, wo, bo, outAttn, M, DD, DD);
}

// round 6
// speedup vs baseline: 1.3271x; 1.2918x over previous
#include <cuda_runtime.h>
#include <cuda_bf16.h>
#include <math.h>

#define BB   4
#define SS   1024
#define DD   512
#define HH   8
#define DKK  64
#define KTOP 204
#define PDIM 64
#define NPAT 8

typedef unsigned long long ull;

// ---- scratch ----
__device__ float g_Qf[BB*SS*DD];
__device__ float g_Kf[BB*SS*DD];
__device__ float g_Vf[BB*SS*DD];
__device__ float g_Ctx[BB*SS*DD];
__device__ float g_S3[(size_t)BB*SS*SS];       // full-dim scores (flat 512-chain)
__device__ unsigned g_Mb[BB*SS*32];            // per-row bitmask (1024 bits)

// ---- packed f32x2 helpers ----
__device__ __forceinline__ ull ff2_pack(float lo, float hi) {
    ull r; asm("mov.b64 %0, {%1, %2};" : "=l"(r) : "f"(lo), "f"(hi)); return r;
}
__device__ __forceinline__ ull ff2_fma(ull a, ull b, ull c) {
    ull d; asm("fma.rn.f32x2 %0, %1, %2, %3;" : "=l"(d) : "l"(a), "l"(b), "l"(c)); return d;
}
__device__ __forceinline__ float2 ff2_unpack(ull v) {
    float lo, hi; asm("mov.b64 {%0, %1}, %2;" : "=f"(lo), "=f"(hi) : "l"(v));
    return make_float2(lo, hi);
}

// ---- bf16 mma helpers ----
__device__ __forceinline__ void mma16816(float* c, const unsigned* a, const unsigned* b) {
    asm volatile("mma.sync.aligned.m16n8k16.row.col.f32.bf16.bf16.f32 "
        "{%0,%1,%2,%3}, {%4,%5,%6,%7}, {%8,%9}, {%0,%1,%2,%3};"
        : "+f"(c[0]), "+f"(c[1]), "+f"(c[2]), "+f"(c[3])
        : "r"(a[0]), "r"(a[1]), "r"(a[2]), "r"(a[3]), "r"(b[0]), "r"(b[1]));
}
__device__ __forceinline__ unsigned bfpack(__nv_bfloat16 a, __nv_bfloat16 b) {
    __nv_bfloat162 t = __halves2bfloat162(a, b);
    return *(unsigned*)&t;
}
__device__ __forceinline__ void bfsplit(float x, __nv_bfloat16& h, __nv_bfloat16& l) {
    h = __float2bfloat16(x);
    l = __float2bfloat16(x - __bfloat162float(h));
}

// ---------------- generic GEMM: C = act(A @ W + bias) ----------------
template<int ACT>
__global__ __launch_bounds__(256)
void gemm_bias_kernel(const float* __restrict__ A, const float* __restrict__ W,
                      const float* __restrict__ bias, float* __restrict__ C,
                      int M, int N, int K) {
    __shared__ __align__(16) float As[16][68];
    __shared__ __align__(16) float Bs[16][68];
    int tid = threadIdx.x;
    int tx = tid & 15, ty = tid >> 4;
    int m0 = blockIdx.y * 64, n0 = blockIdx.x * 64;
    ull acc2[4][2];
    #pragma unroll
    for (int i = 0; i < 4; i++) { acc2[i][0] = 0ull; acc2[i][1] = 0ull; }
    for (int k0 = 0; k0 < K; k0 += 16) {
        #pragma unroll
        for (int l = 0; l < 4; l++) {
            int idx = tid + l * 256;
            int r = idx >> 4, c = idx & 15;
            As[c][r] = A[(size_t)(m0 + r) * K + k0 + c];
        }
        #pragma unroll
        for (int l = 0; l < 4; l++) {
            int idx = tid + l * 256;
            int r = idx >> 6, c = idx & 63;
            Bs[r][c] = W[(size_t)(k0 + r) * N + n0 + c];
        }
        __syncthreads();
        #pragma unroll
        for (int kk = 0; kk < 16; kk++) {
            float4 a4 = *(const float4*)&As[kk][ty * 4];
            float4 b4 = *(const float4*)&Bs[kk][tx * 4];
            ull b01 = ff2_pack(b4.x, b4.y);
            ull b23 = ff2_pack(b4.z, b4.w);
            ull aa;
            aa = ff2_pack(a4.x, a4.x);
            acc2[0][0] = ff2_fma(aa, b01, acc2[0][0]);
            acc2[0][1] = ff2_fma(aa, b23, acc2[0][1]);
            aa = ff2_pack(a4.y, a4.y);
            acc2[1][0] = ff2_fma(aa, b01, acc2[1][0]);
            acc2[1][1] = ff2_fma(aa, b23, acc2[1][1]);
            aa = ff2_pack(a4.z, a4.z);
            acc2[2][0] = ff2_fma(aa, b01, acc2[2][0]);
            acc2[2][1] = ff2_fma(aa, b23, acc2[2][1]);
            aa = ff2_pack(a4.w, a4.w);
            acc2[3][0] = ff2_fma(aa, b01, acc2[3][0]);
            acc2[3][1] = ff2_fma(aa, b23, acc2[3][1]);
        }
        __syncthreads();
    }
    #pragma unroll
    for (int i = 0; i < 4; i++) {
        int m = m0 + ty * 4 + i;
        #pragma unroll
        for (int jp = 0; jp < 2; jp++) {
            float2 v2 = ff2_unpack(acc2[i][jp]);
            int n = n0 + tx * 4 + jp * 2;
            float v = v2.x + bias[n];
            if (ACT == 1) v = fmaxf(v, 0.0f);
            if (ACT == 2) v = tanhf(v);
            C[(size_t)m * N + n] = v;
            v = v2.y + bias[n + 1];
            if (ACT == 1) v = fmaxf(v, 0.0f);
            if (ACT == 2) v = tanhf(v);
            C[(size_t)m * N + n + 1] = v;
        }
    }
}

// ---------------- merged QKV projection (bit-exact chains, load-bearing) ----------------
__global__ __launch_bounds__(256)
void qkv_kernel(const float* __restrict__ q, const float* __restrict__ k,
                const float* __restrict__ v,
                const float* __restrict__ wq, const float* __restrict__ bq,
                const float* __restrict__ wk, const float* __restrict__ bk,
                const float* __restrict__ wv, const float* __restrict__ bv,
                float* __restrict__ Qf, float* __restrict__ Kf, float* __restrict__ Vf) {
    __shared__ __align__(16) float As[16][68];
    __shared__ __align__(16) float Bs[16][68];
    const float *A, *W, *bias; float* C;
    if (blockIdx.z == 0)      { A = q; W = wq; bias = bq; C = Qf; }
    else if (blockIdx.z == 1) { A = k; W = wk; bias = bk; C = Kf; }
    else                      { A = v; W = wv; bias = bv; C = Vf; }
    const int N = DD, K = DD;
    int tid = threadIdx.x;
    int tx = tid & 15, ty = tid >> 4;
    int m0 = blockIdx.y * 64, n0 = blockIdx.x * 64;
    ull acc2[4][2];
    #pragma unroll
    for (int i = 0; i < 4; i++) { acc2[i][0] = 0ull; acc2[i][1] = 0ull; }
    for (int k0 = 0; k0 < K; k0 += 16) {
        #pragma unroll
        for (int l = 0; l < 4; l++) {
            int idx = tid + l * 256;
            int r = idx >> 4, c = idx & 15;
            As[c][r] = A[(size_t)(m0 + r) * K + k0 + c];
        }
        #pragma unroll
        for (int l = 0; l < 4; l++) {
            int idx = tid + l * 256;
            int r = idx >> 6, c = idx & 63;
            Bs[r][c] = W[(size_t)(k0 + r) * N + n0 + c];
        }
        __syncthreads();
        #pragma unroll
        for (int kk = 0; kk < 16; kk++) {
            float4 a4 = *(const float4*)&As[kk][ty * 4];
            float4 b4 = *(const float4*)&Bs[kk][tx * 4];
            ull b01 = ff2_pack(b4.x, b4.y);
            ull b23 = ff2_pack(b4.z, b4.w);
            ull aa;
            aa = ff2_pack(a4.x, a4.x);
            acc2[0][0] = ff2_fma(aa, b01, acc2[0][0]);
            acc2[0][1] = ff2_fma(aa, b23, acc2[0][1]);
            aa = ff2_pack(a4.y, a4.y);
            acc2[1][0] = ff2_fma(aa, b01, acc2[1][0]);
            acc2[1][1] = ff2_fma(aa, b23, acc2[1][1]);
            aa = ff2_pack(a4.z, a4.z);
            acc2[2][0] = ff2_fma(aa, b01, acc2[2][0]);
            acc2[2][1] = ff2_fma(aa, b23, acc2[2][1]);
            aa = ff2_pack(a4.w, a4.w);
            acc2[3][0] = ff2_fma(aa, b01, acc2[3][0]);
            acc2[3][1] = ff2_fma(aa, b23, acc2[3][1]);
        }
        __syncthreads();
    }
    #pragma unroll
    for (int i = 0; i < 4; i++) {
        int m = m0 + ty * 4 + i;
        #pragma unroll
        for (int jp = 0; jp < 2; jp++) {
            float2 v2 = ff2_unpack(acc2[i][jp]);
            int n = n0 + tx * 4 + jp * 2;
            C[(size_t)m * N + n]     = v2.x + bias[n];
            C[(size_t)m * N + n + 1] = v2.y + bias[n + 1];
        }
    }
}

// ------------- S3 only: flat ascending-k 512-chain (bit-exact, load-bearing) -------------
__global__ __launch_bounds__(256)
void s3_kernel(const float* __restrict__ Qf, const float* __restrict__ Kf,
               float* __restrict__ S3) {
    __shared__ float Qs[64][65];
    __shared__ float Ks[64][65];
    int b = blockIdx.z;
    int i0 = blockIdx.y * 64, j0 = blockIdx.x * 64;
    int tid = threadIdx.x, tx = tid & 15, ty = tid >> 4;
    ull s32[4][2];
    #pragma unroll
    for (int i = 0; i < 4; i++) { s32[i][0] = 0ull; s32[i][1] = 0ull; }
    for (int h = 0; h < HH; h++) {
        #pragma unroll
        for (int l = 0; l < 16; l++) {
            int idx = tid + l * 256;
            int r = idx >> 6, c = idx & 63;
            Qs[r][c] = Qf[(size_t)(b * SS + i0 + r) * DD + h * 64 + c];
            Ks[r][c] = Kf[(size_t)(b * SS + j0 + r) * DD + h * 64 + c];
        }
        __syncthreads();
        #pragma unroll
        for (int k = 0; k < 64; k++) {
            float a0 = Qs[ty * 4 + 0][k], a1 = Qs[ty * 4 + 1][k];
            float a2 = Qs[ty * 4 + 2][k], a3 = Qs[ty * 4 + 3][k];
            float v0 = Ks[tx * 4 + 0][k], v1 = Ks[tx * 4 + 1][k];
            float v2 = Ks[tx * 4 + 2][k], v3 = Ks[tx * 4 + 3][k];
            ull b01 = ff2_pack(v0, v1);
            ull b23 = ff2_pack(v2, v3);
            ull aa;
            aa = ff2_pack(a0, a0);
            s32[0][0] = ff2_fma(aa, b01, s32[0][0]);
            s32[0][1] = ff2_fma(aa, b23, s32[0][1]);
            aa = ff2_pack(a1, a1);
            s32[1][0] = ff2_fma(aa, b01, s32[1][0]);
            s32[1][1] = ff2_fma(aa, b23, s32[1][1]);
            aa = ff2_pack(a2, a2);
            s32[2][0] = ff2_fma(aa, b01, s32[2][0]);
            s32[2][1] = ff2_fma(aa, b23, s32[2][1]);
            aa = ff2_pack(a3, a3);
            s32[3][0] = ff2_fma(aa, b01, s32[3][0]);
            s32[3][1] = ff2_fma(aa, b23, s32[3][1]);
        }
        __syncthreads();
    }
    size_t b3 = ((size_t)b * SS + i0) * SS + j0;
    #pragma unroll
    for (int i = 0; i < 4; i++)
        #pragma unroll
        for (int jp = 0; jp < 2; jp++) {
            float2 v2 = ff2_unpack(s32[i][jp]);
            size_t o = b3 + (size_t)(ty * 4 + i) * SS + tx * 4 + jp * 2;
            S3[o]     = v2.x * 0.125f;
            S3[o + 1] = v2.y * 0.125f;
        }
}

// ------------- row-wise top-204 -> float mask (x8 heads) + bitmask -------------
__global__ __launch_bounds__(256)
void topk_mask_kernel(const float* __restrict__ S3, float* __restrict__ maskOut,
                      unsigned* __restrict__ Mb) {
    __shared__ unsigned keys[1024];
    __shared__ int hist[256];
    __shared__ unsigned s_prefix;
    __shared__ int s_rem;
    int row = blockIdx.x;
    int b = row >> 10, i = row & 1023;
    int tid = threadIdx.x;
    const float* src = S3 + (size_t)row * SS;
    #pragma unroll
    for (int l = 0; l < 4; l++) {
        int j = tid + l * 256;
        unsigned bits = __float_as_uint(src[j]);
        keys[j] = (bits & 0x80000000u) ? ~bits : (bits | 0x80000000u);
    }
    if (tid == 0) { s_prefix = 0u; s_rem = KTOP; }
    __syncthreads();
    for (int pass = 0; pass < 4; pass++) {
        int shift = 24 - pass * 8;
        hist[tid] = 0;
        __syncthreads();
        unsigned pref = s_prefix;
        #pragma unroll
        for (int l = 0; l < 4; l++) {
            unsigned key = keys[tid + l * 256];
            bool match = (pass == 0) || ((key >> (shift + 8)) == (pref >> (shift + 8)));
            if (match) atomicAdd(&hist[(key >> shift) & 255], 1);
        }
        __syncthreads();
        if (tid == 0) {
            int c = 0, rem = s_rem; unsigned chosen = 0;
            for (int bin = 255; bin >= 0; bin--) {
                c += hist[bin];
                if (c >= rem) { chosen = (unsigned)bin; s_rem = rem - (c - hist[bin]); break; }
            }
            s_prefix = pref | (chosen << shift);
        }
        __syncthreads();
    }
    unsigned T = s_prefix;
    int need = s_rem;
    size_t maskBase = (size_t)b * HH * SS * SS + (size_t)i * SS;
    #pragma unroll
    for (int l = 0; l < 4; l++) {
        int j = tid + l * 256;
        unsigned key = keys[j];
        float m = 0.0f;
        if (key > T) m = 1.0f;
        else if (key == T) {
            int cnt = 0;
            for (int jj = 0; jj < j; jj++) cnt += (keys[jj] == T) ? 1 : 0;
            if (cnt < need) m = 1.0f;
        }
        unsigned bal = __ballot_sync(0xffffffffu, m > 0.0f);
        if ((tid & 31) == 0)
            Mb[(size_t)row * 32 + l * 8 + (tid >> 5)] = bal;
        #pragma unroll
        for (int h = 0; h < HH; h++)
            maskOut[maskBase + (size_t)h * SS * SS + j] = m;
    }
}

// ------------- fused tensor-core attention -------------
// Per (b,h,128-row tile): S = Q K^T (bf16x3 MMA), mask bits, exp, P V (bf16x3 MMA),
// rowsum normalize. Never materializes Sc.
#define BSTR 72   // bf16 smem row stride (conflict-free frag loads)
__global__ void attn_tc_kernel(const float* __restrict__ Qf, const float* __restrict__ Kf,
                               const float* __restrict__ Vf, const unsigned* __restrict__ Mb,
                               float* __restrict__ Ctx) {
    extern __shared__ __nv_bfloat16 sb[];
    __nv_bfloat16* Qh = sb;                    // 128 x BSTR
    __nv_bfloat16* Ql = sb + 128 * BSTR;
    __nv_bfloat16* Kh = sb + 256 * BSTR;       // 64 x BSTR
    __nv_bfloat16* Kl = sb + 320 * BSTR;
    __nv_bfloat16* Vh = sb + 384 * BSTR;       // transposed: [d][j]
    __nv_bfloat16* Vl = sb + 448 * BSTR;
    int bh = blockIdx.y;
    int b = bh >> 3, h = bh & 7;
    int i0 = blockIdx.x * 128;
    int tid = threadIdx.x;
    int w = tid >> 5, lane = tid & 31;
    int g = lane >> 2, tig = lane & 3;

    // load Q tile (128x64), split hi/lo
    for (int l = 0; l < 32; l++) {
        int idx = tid + l * 256;
        int r = idx >> 6, c = idx & 63;
        float qv = Qf[(size_t)(b * SS + i0 + r) * DD + h * 64 + c];
        __nv_bfloat16 hh, ll; bfsplit(qv, hh, ll);
        Qh[r * BSTR + c] = hh;
        Ql[r * BSTR + c] = ll;
    }
    __syncthreads();

    // Q A-fragments (held all kernel)
    unsigned aQh[4][4], aQl[4][4];
    int rr = w * 16 + g;
    #pragma unroll
    for (int kc = 0; kc < 4; kc++) {
        aQh[kc][0] = *(const unsigned*)&Qh[rr * BSTR + kc * 16 + 2 * tig];
        aQh[kc][1] = *(const unsigned*)&Qh[(rr + 8) * BSTR + kc * 16 + 2 * tig];
        aQh[kc][2] = *(const unsigned*)&Qh[rr * BSTR + kc * 16 + 2 * tig + 8];
        aQh[kc][3] = *(const unsigned*)&Qh[(rr + 8) * BSTR + kc * 16 + 2 * tig + 8];
        aQl[kc][0] = *(const unsigned*)&Ql[rr * BSTR + kc * 16 + 2 * tig];
        aQl[kc][1] = *(const unsigned*)&Ql[(rr + 8) * BSTR + kc * 16 + 2 * tig];
        aQl[kc][2] = *(const unsigned*)&Ql[rr * BSTR + kc * 16 + 2 * tig + 8];
        aQl[kc][3] = *(const unsigned*)&Ql[(rr + 8) * BSTR + kc * 16 + 2 * tig + 8];
    }

    float oacc[8][4];
    #pragma unroll
    for (int dn = 0; dn < 8; dn++)
        #pragma unroll
        for (int r = 0; r < 4; r++) oacc[dn][r] = 0.0f;
    float rs0 = 0.0f, rs1 = 0.0f;
    int row0 = i0 + w * 16 + g, row1 = row0 + 8;
    const unsigned* mrow0 = Mb + (size_t)(b * SS + row0) * 32;
    const unsigned* mrow1 = Mb + (size_t)(b * SS + row1) * 32;

    for (int j0 = 0; j0 < SS; j0 += 64) {
        __syncthreads();
        // load K (j-major) and V (transposed to d-major), split hi/lo
        for (int l = 0; l < 16; l++) {
            int idx = tid + l * 256;
            int r = idx >> 6, c = idx & 63;       // r=j-local, c=dk/d
            size_t go = (size_t)(b * SS + j0 + r) * DD + h * 64 + c;
            float kv = Kf[go];
            __nv_bfloat16 hh, ll; bfsplit(kv, hh, ll);
            Kh[r * BSTR + c] = hh;
            Kl[r * BSTR + c] = ll;
            float vv = Vf[go];
            bfsplit(vv, hh, ll);
            Vh[c * BSTR + r] = hh;
            Vl[c * BSTR + r] = ll;
        }
        __syncthreads();

        unsigned aPh[4][4], aPl[4][4];
        #pragma unroll
        for (int jn = 0; jn < 8; jn++) {
            float s[4] = {0.f, 0.f, 0.f, 0.f};
            #pragma unroll
            for (int kc = 0; kc < 4; kc++) {
                unsigned bh2[2], bl2[2];
                int krow = (jn * 8 + g) * BSTR + kc * 16 + 2 * tig;
                bh2[0] = *(const unsigned*)&Kh[krow];
                bh2[1] = *(const unsigned*)&Kh[krow + 8];
                bl2[0] = *(const unsigned*)&Kl[krow];
                bl2[1] = *(const unsigned*)&Kl[krow + 8];
                mma16816(s, aQh[kc], bh2);
                mma16816(s, aQl[kc], bh2);
                mma16816(s, aQh[kc], bl2);
            }
            int j = j0 + jn * 8 + 2 * tig;
            unsigned w0 = mrow0[j >> 5], w1 = mrow1[j >> 5];
            float p0 = ((w0 >> (j & 31)) & 1u) ? __expf(s[0] * 0.125f) : 0.0f;
            float p1 = ((w0 >> ((j + 1) & 31)) & 1u) ? __expf(s[1] * 0.125f) : 0.0f;
            float p2 = ((w1 >> (j & 31)) & 1u) ? __expf(s[2] * 0.125f) : 0.0f;
            float p3 = ((w1 >> ((j + 1) & 31)) & 1u) ? __expf(s[3] * 0.125f) : 0.0f;
            rs0 += p0 + p1;
            rs1 += p2 + p3;
            __nv_bfloat16 h0, l0, h1, l1, h2, l2, h3, l3;
            bfsplit(p0, h0, l0); bfsplit(p1, h1, l1);
            bfsplit(p2, h2, l2); bfsplit(p3, h3, l3);
            int kc = jn >> 1, half = (jn & 1) ? 2 : 0;
            aPh[kc][half + 0] = bfpack(h0, h1);
            aPh[kc][half + 1] = bfpack(h2, h3);
            aPl[kc][half + 0] = bfpack(l0, l1);
            aPl[kc][half + 1] = bfpack(l2, l3);
        }
        // O += P @ V
        #pragma unroll
        for (int dn = 0; dn < 8; dn++) {
            #pragma unroll
            for (int kc = 0; kc < 4; kc++) {
                unsigned bvh[2], bvl[2];
                int vrow = (dn * 8 + g) * BSTR + kc * 16 + 2 * tig;
                bvh[0] = *(const unsigned*)&Vh[vrow];
                bvh[1] = *(const unsigned*)&Vh[vrow + 8];
                bvl[0] = *(const unsigned*)&Vl[vrow];
                bvl[1] = *(const unsigned*)&Vl[vrow + 8];
                mma16816(oacc[dn], aPh[kc], bvh);
                mma16816(oacc[dn], aPl[kc], bvh);
                mma16816(oacc[dn], aPh[kc], bvl);
            }
        }
    }
    // rowsum reduce across quad (tig lanes), normalize, write
    rs0 += __shfl_xor_sync(0xffffffffu, rs0, 1);
    rs0 += __shfl_xor_sync(0xffffffffu, rs0, 2);
    rs1 += __shfl_xor_sync(0xffffffffu, rs1, 1);
    rs1 += __shfl_xor_sync(0xffffffffu, rs1, 2);
    float inv0 = 1.0f / rs0, inv1 = 1.0f / rs1;
    #pragma unroll
    for (int dn = 0; dn < 8; dn++) {
        int d = h * 64 + dn * 8 + 2 * tig;
        float2 v0 = make_float2(oacc[dn][0] * inv0, oacc[dn][1] * inv0);
        float2 v1 = make_float2(oacc[dn][2] * inv1, oacc[dn][3] * inv1);
        *(float2*)&Ctx[(size_t)(b * SS + row0) * DD + d] = v0;
        *(float2*)&Ctx[(size_t)(b * SS + row1) * DD + d] = v1;
    }
}

// ------------- fused pattern branch -------------
__global__ __launch_bounds__(256)
void pattern_fused_kernel(const float* __restrict__ q,
                          const float* __restrict__ pw1, const float* __restrict__ pb1,
                          const float* __restrict__ pw2, const float* __restrict__ pb2,
                          const float* __restrict__ bank, const float* __restrict__ gate,
                          float* __restrict__ outP) {
    __shared__ float As[16][33];
    __shared__ float Bs[16][65];
    __shared__ float H1[32][65];
    __shared__ float Enc[32][65];
    int tid = threadIdx.x, tx = tid & 15, ty = tid >> 4;
    int m0 = blockIdx.x * 32;
    float acc[2][4] = {};
    for (int k0 = 0; k0 < DD; k0 += 16) {
        #pragma unroll
        for (int l = 0; l < 2; l++) {
            int idx = tid + l * 256;
            int r = idx >> 4, c = idx & 15;
            As[c][r] = q[(size_t)(m0 + r) * DD + k0 + c];
        }
        #pragma unroll
        for (int l = 0; l < 4; l++) {
            int idx = tid + l * 256;
            int r = idx >> 6, c = idx & 63;
            Bs[r][c] = pw1[(size_t)(k0 + r) * PDIM + c];
        }
        __syncthreads();
        #pragma unroll
        for (int kk = 0; kk < 16; kk++) {
            float a0 = As[kk][ty * 2], a1 = As[kk][ty * 2 + 1];
            #pragma unroll
            for (int j = 0; j < 4; j++) {
                float bb = Bs[kk][tx * 4 + j];
                acc[0][j] = fmaf(a0, bb, acc[0][j]);
                acc[1][j] = fmaf(a1, bb, acc[1][j]);
            }
        }
        __syncthreads();
    }
    #pragma unroll
    for (int i = 0; i < 2; i++)
        #pragma unroll
        for (int j = 0; j < 4; j++)
            H1[ty * 2 + i][tx * 4 + j] = fmaxf(acc[i][j] + pb1[tx * 4 + j], 0.0f);
    __syncthreads();
    float acc2[2][4] = {};
    for (int k0 = 0; k0 < PDIM; k0 += 16) {
        #pragma unroll
        for (int l = 0; l < 4; l++) {
            int idx = tid + l * 256;
            int r = idx >> 6, c = idx & 63;
            Bs[idx >> 6][c] = pw2[(size_t)(k0 + r) * PDIM + c];
        }
        __syncthreads();
        #pragma unroll
        for (int kk = 0; kk < 16; kk++) {
            float a0 = H1[ty * 2][k0 + kk], a1 = H1[ty * 2 + 1][k0 + kk];
            #pragma unroll
            for (int j = 0; j < 4; j++) {
                float bb = Bs[kk][tx * 4 + j];
                acc2[0][j] = fmaf(a0, bb, acc2[0][j]);
                acc2[1][j] = fmaf(a1, bb, acc2[1][j]);
            }
        }
        __syncthreads();
    }
    #pragma unroll
    for (int i = 0; i < 2; i++)
        #pragma unroll
        for (int j = 0; j < 4; j++)
            Enc[ty * 2 + i][tx * 4 + j] = tanhf(acc2[i][j] + pb2[tx * 4 + j]);
    __syncthreads();
    int row = tid >> 3, p = tid & 7;
    float d = 0.0f;
    #pragma unroll
    for (int k = 0; k < PDIM; k++)
        d = fmaf(Enc[row][k], bank[p * PDIM + k], d);
    float s = d * 0.125f;
    float mx = s;
    #pragma unroll
    for (int o = 1; o < 8; o <<= 1) mx = fmaxf(mx, __shfl_xor_sync(0xffffffffu, mx, o));
    float e = expf(s - mx);
    float sum = e;
    #pragma unroll
    for (int o = 1; o < 8; o <<= 1) sum += __shfl_xor_sync(0xffffffffu, sum, o);
    outP[(size_t)(m0 + row) * NPAT + p] = e / sum * gate[p];
}

extern "C" void kernel_launch(void* const* d_in, const int* in_sizes, int n_in,
                              void* d_out, int out_size) {
    const float* query = (const float*)d_in[0];
    const float* key   = (const float*)d_in[1];
    const float* value = (const float*)d_in[2];
    const float* wq = (const float*)d_in[3];  const float* bq = (const float*)d_in[4];
    const float* wk = (const float*)d_in[5];  const float* bk = (const float*)d_in[6];
    const float* wv = (const float*)d_in[7];  const float* bv = (const float*)d_in[8];
    const float* wo = (const float*)d_in[9];  const float* bo = (const float*)d_in[10];
    const float* pw1 = (const float*)d_in[11]; const float* pb1 = (const float*)d_in[12];
    const float* pw2 = (const float*)d_in[13]; const float* pb2 = (const float*)d_in[14];
    const float* bank = (const float*)d_in[15];
    const float* gate = (const float*)d_in[16];
    float* out = (float*)d_out;

    void *pQf, *pKf, *pVf, *pCtx, *pS3, *pMb;
    cudaGetSymbolAddress(&pQf, g_Qf);
    cudaGetSymbolAddress(&pKf, g_Kf);
    cudaGetSymbolAddress(&pVf, g_Vf);
    cudaGetSymbolAddress(&pCtx, g_Ctx);
    cudaGetSymbolAddress(&pS3, g_S3);
    cudaGetSymbolAddress(&pMb, g_Mb);
    float* Qf = (float*)pQf;   float* Kf = (float*)pKf;
    float* Vf = (float*)pVf;   float* Ctx = (float*)pCtx;
    float* S3 = (float*)pS3;   unsigned* Mb = (unsigned*)pMb;

    const size_t maskOff  = (size_t)BB * SS * DD;
    const size_t patOff   = maskOff + (size_t)BB * HH * SS * SS;
    float* outAttn = out;
    float* outMask = out + maskOff;
    float* outPat  = out + patOff;

    const int M = BB * SS;   // 4096
    dim3 blk(256);

    const int ATTN_SMEM = 512 * BSTR * sizeof(__nv_bfloat16);  // 73728 B
    cudaFuncSetAttribute(attn_tc_kernel,
                         cudaFuncAttributeMaxDynamicSharedMemorySize, ATTN_SMEM);

    // QKV projections (bit-exact chains, load-bearing for mask)
    qkv_kernel<<<dim3(DD / 64, M / 64, 3), blk>>>(query, key, value,
                                                  wq, bq, wk, bk, wv, bv,
                                                  Qf, Kf, Vf);

    // fused pattern branch
    pattern_fused_kernel<<<dim3(M / 32), blk>>>(query, pw1, pb1, pw2, pb2,
                                                bank, gate, outPat);

    // flat-chain full-dim scores (exact)
    s3_kernel<<<dim3(SS / 64, SS / 64, BB), blk>>>(Qf, Kf, S3);

    // top-204: float mask output (x8 heads) + bitmask scratch
    topk_mask_kernel<<<dim3(BB * SS), blk>>>(S3, outMask, Mb);

    // fused tensor-core attention (bf16x3 QK + exp + bf16x3 PV)
    attn_tc_kernel<<<dim3(SS / 128, BB * HH), blk, ATTN_SMEM>>>(Qf, Kf, Vf, Mb, Ctx);

    // output projection
    gemm_bias_kernel<0><<<dim3(DD / 64, M / 64), blk>>>(Ctx, wo, bo, outAttn, M, DD, DD);
}